// round 5
// baseline (speedup 1.0000x reference)
#include <cuda_runtime.h>
#include <cstdint>

#define NB 256
#define NS 32
#define NV 10000
#define DEMB 512
#define DHID 1024
#define DIMG 2048
#define BOS_TOK 1
#define EOS_TOK 2

// ---------------- device scratch (static, no allocations) ----------------
__device__ float g_h0[NB * DHID];
__device__ float g_h1[NB * DHID];
__device__ float g_x [NB * DEMB];          // relu(emb[token]) for current step
__device__ float g_G1[NB * 3 * DHID];      // x @ w_ih^T
__device__ float g_G2[NB * 3 * DHID];      // h @ w_hh^T
__device__ float g_WbT[DHID * DIMG];       // W_b transposed -> [DHID][DIMG]
__device__ unsigned long long g_amax[NB];  // packed (value,index) argmax per row
__device__ int g_tok[NS * NB];

// ---------------- f32x2 helpers (FFMA2: 2x fp32 FMA throughput) ----------------
__device__ __forceinline__ unsigned long long dup2(float a) {
    unsigned long long r;
    asm("mov.b64 %0, {%1, %1};" : "=l"(r) : "f"(a));
    return r;
}
__device__ __forceinline__ void ffma2(unsigned long long& d, unsigned long long a, unsigned long long b) {
    asm("fma.rn.f32x2 %0, %1, %2, %0;" : "+l"(d) : "l"(a), "l"(b));
}
__device__ __forceinline__ float lo32(unsigned long long v) {
    return __uint_as_float((unsigned)(v & 0xFFFFFFFFull));
}
__device__ __forceinline__ float hi32(unsigned long long v) {
    return __uint_as_float((unsigned)(v >> 32));
}

// order-preserving (float,index) pack; max => max value, ties => smallest index
__device__ __forceinline__ unsigned long long packmax(float v, int idx) {
    unsigned int b = __float_as_uint(v);
    b = (b & 0x80000000u) ? ~b : (b | 0x80000000u);
    return ((unsigned long long)b << 32) | (unsigned long long)(0xFFFFFFFFu - (unsigned)idx);
}

// ---------------- W_b transpose: [DIMG][DHID] -> [DHID][DIMG] ----------------
__global__ void transpose_wb(const float* __restrict__ Wb) {
    __shared__ float t[32][33];
    int k0 = blockIdx.x * 32;
    int n0 = blockIdx.y * 32;
    for (int i = threadIdx.y; i < 32; i += 8)
        t[i][threadIdx.x] = Wb[(size_t)(k0 + i) * DHID + n0 + threadIdx.x];
    __syncthreads();
    for (int i = threadIdx.y; i < 32; i += 8)
        g_WbT[(size_t)(n0 + i) * DIMG + k0 + threadIdx.x] = t[threadIdx.x][i];
}

// ---------------- zero the one-hot output ----------------
__global__ void zero_out(float4* o, long long n4) {
    long long i = (long long)blockIdx.x * blockDim.x + threadIdx.x;
    if (i < n4) o[i] = make_float4(0.f, 0.f, 0.f, 0.f);
}

// ---------------- init: x0 = relu(emb[BOS]), amax reset ----------------
__global__ void init_kernel(const float* __restrict__ emb) {
    int b = blockIdx.x;
    if (threadIdx.x == 0) g_amax[b] = 0ull;
    for (int k = threadIdx.x; k < DEMB; k += 128)
        g_x[b * DEMB + k] = fmaxf(emb[(size_t)BOS_TOK * DEMB + k], 0.f);
}

// ---------------- 32x128 GEMM (C = A[M,K] * B[N,K]^T), dual dispatch over z ----------------
// High-occupancy tile: 256 thr, up to 3 CTAs/SM. Used for gates (z=2) and h0 (z=1).
__global__ __launch_bounds__(256, 3)
void gemm32_dual(const float* __restrict__ A0, const float* __restrict__ B0, float* __restrict__ C0, int K0,
                 const float* __restrict__ A1, const float* __restrict__ B1, float* __restrict__ C1, int K1,
                 int N)
{
    const float* A; const float* Bm; float* C; int K;
    if (blockIdx.z == 0) { A = A0; Bm = B0; C = C0; K = K0; }
    else                 { A = A1; Bm = B1; C = C1; K = K1; }

    __shared__ float As[2][16][36];
    __shared__ float Bs[2][16][128];

    const int tid = threadIdx.x;
    const int tx8 = (tid & 15) * 8;
    const int ty2 = (tid >> 4) * 2;
    const int bm = blockIdx.y * 32;
    const int bn = blockIdx.x * 128;

    const int arow = tid >> 3;        // 0..31
    const int akq  = (tid & 7) * 2;   // 0..14 step 2
    const int brow = tid >> 2;        // 0..63
    const int bkq  = (tid & 3) * 4;

    const float* Ag  = A  + (size_t)(bm + arow) * K + akq;
    const float* Bg0 = Bm + (size_t)(bn + brow) * K + bkq;
    const float* Bg1 = Bg0 + (size_t)64 * K;

    unsigned long long acc[2][4];
#pragma unroll
    for (int i = 0; i < 2; i++)
#pragma unroll
        for (int p = 0; p < 4; p++) acc[i][p] = 0ull;

    float2 ra; float4 rb0, rb1;
    auto LD = [&](int kt) {
        ra  = *(const float2*)(Ag  + kt * 16);
        rb0 = *(const float4*)(Bg0 + kt * 16);
        rb1 = *(const float4*)(Bg1 + kt * 16);
    };
    auto ST = [&](int buf) {
        As[buf][akq + 0][arow] = ra.x;  As[buf][akq + 1][arow] = ra.y;
        Bs[buf][bkq + 0][brow] = rb0.x; Bs[buf][bkq + 1][brow] = rb0.y;
        Bs[buf][bkq + 2][brow] = rb0.z; Bs[buf][bkq + 3][brow] = rb0.w;
        Bs[buf][bkq + 0][brow + 64] = rb1.x; Bs[buf][bkq + 1][brow + 64] = rb1.y;
        Bs[buf][bkq + 2][brow + 64] = rb1.z; Bs[buf][bkq + 3][brow + 64] = rb1.w;
    };

    LD(0); ST(0);
    __syncthreads();
    const int KT = K >> 4;
    int cur = 0;
    for (int kt = 0; kt < KT; ++kt) {
        if (kt + 1 < KT) LD(kt + 1);

        float2 af[2]; ulonglong2 bl[2], bh[2];
        af[0] = *(const float2*)&As[cur][0][ty2];
        bl[0] = *(const ulonglong2*)&Bs[cur][0][tx8];
        bh[0] = *(const ulonglong2*)&Bs[cur][0][tx8 + 4];
#pragma unroll
        for (int k = 0; k < 16; ++k) {
            const int cu = k & 1, nx = cu ^ 1;
            if (k < 15) {
                af[nx] = *(const float2*)&As[cur][k + 1][ty2];
                bl[nx] = *(const ulonglong2*)&Bs[cur][k + 1][tx8];
                bh[nx] = *(const ulonglong2*)&Bs[cur][k + 1][tx8 + 4];
            }
            unsigned long long a0 = dup2(af[cu].x);
            unsigned long long a1 = dup2(af[cu].y);
            unsigned long long bd[4] = {bl[cu].x, bl[cu].y, bh[cu].x, bh[cu].y};
#pragma unroll
            for (int p = 0; p < 4; p++) ffma2(acc[0][p], a0, bd[p]);
#pragma unroll
            for (int p = 0; p < 4; p++) ffma2(acc[1][p], a1, bd[p]);
        }
        if (kt + 1 < KT) ST(cur ^ 1);
        __syncthreads();
        cur ^= 1;
    }

#pragma unroll
    for (int i = 0; i < 2; i++) {
        float* crow = C + (size_t)(bm + ty2 + i) * N + bn + tx8;
#pragma unroll
        for (int p = 0; p < 4; p++) {
            crow[2 * p]     = lo32(acc[i][p]);
            crow[2 * p + 1] = hi32(acc[i][p]);
        }
    }
}

// ---------------- GRU elementwise (float4): h_new from G1, G2, biases, h_old ----------------
__global__ void gru_elem(const float* __restrict__ b_ih, const float* __restrict__ b_hh,
                         const float* __restrict__ hOld, float* __restrict__ hNew)
{
    int idx = blockIdx.x * blockDim.x + threadIdx.x;   // NB*DHID/4
    int m = idx >> 8;                 // DHID/4 = 256 float4 per row
    int j = (idx & 255) * 4;
    const float* G1 = g_G1 + (size_t)m * (3 * DHID);
    const float* G2 = g_G2 + (size_t)m * (3 * DHID);

    float4 ir = *(const float4*)(G1 + j);
    float4 iz = *(const float4*)(G1 + DHID + j);
    float4 in_ = *(const float4*)(G1 + 2 * DHID + j);
    float4 hr = *(const float4*)(G2 + j);
    float4 hz = *(const float4*)(G2 + DHID + j);
    float4 hn = *(const float4*)(G2 + 2 * DHID + j);
    float4 bir = *(const float4*)(b_ih + j);
    float4 biz = *(const float4*)(b_ih + DHID + j);
    float4 bin = *(const float4*)(b_ih + 2 * DHID + j);
    float4 bhr = *(const float4*)(b_hh + j);
    float4 bhz = *(const float4*)(b_hh + DHID + j);
    float4 bhn = *(const float4*)(b_hh + 2 * DHID + j);
    float4 ho = *(const float4*)(hOld + (size_t)m * DHID + j);

    float4 res;
#define GRU1(c) { \
        float r = 1.f / (1.f + expf(-((ir.c + bir.c) + (hr.c + bhr.c)))); \
        float z = 1.f / (1.f + expf(-((iz.c + biz.c) + (hz.c + bhz.c)))); \
        float n = tanhf((in_.c + bin.c) + r * (hn.c + bhn.c)); \
        res.c = (1.f - z) * n + z * ho.c; }
    GRU1(x) GRU1(y) GRU1(z) GRU1(w)
#undef GRU1
    *(float4*)(hNew + (size_t)m * DHID + j) = res;
}

// ---------------- logits GEMM (64x128 tile) fused with +bias +gumbel + argmax ----------------
__global__ __launch_bounds__(256, 2)
void gemm_logits(const float* __restrict__ A, const float* __restrict__ W,
                 const float* __restrict__ bout, const float* __restrict__ gumbel, int step)
{
    const int N = NV, K = DHID;

    __shared__ float As[2][16][68];
    __shared__ float Bs[2][16][128];
    __shared__ unsigned long long rowmax[64];
    __shared__ float bo[128];

    const int tid = threadIdx.x;
    const int tx8 = (tid & 15) * 8;
    const int ty4 = (tid >> 4) * 4;
    const int bm = blockIdx.y * 64;
    const int bn = blockIdx.x * 128;

    const int row = tid >> 2;        // 0..63
    const int kq  = (tid & 3) * 4;

    const float* Ag = A + (size_t)(bm + row) * K + kq;
    const int brow0 = bn + row;
    const int brow1 = brow0 + 64;
    const float* Bg0 = W + (size_t)brow0 * K + kq;
    const float* Bg1 = W + (size_t)brow1 * K + kq;

    unsigned long long acc[4][4];
#pragma unroll
    for (int i = 0; i < 4; i++)
#pragma unroll
        for (int p = 0; p < 4; p++) acc[i][p] = 0ull;

    float4 ra, rb0, rb1;
    const float4 f4z = make_float4(0.f, 0.f, 0.f, 0.f);
    auto LD = [&](int kt) {
        ra  = *(const float4*)(Ag + kt * 16);
        rb0 = (brow0 < N) ? *(const float4*)(Bg0 + kt * 16) : f4z;
        rb1 = (brow1 < N) ? *(const float4*)(Bg1 + kt * 16) : f4z;
    };
    auto ST = [&](int buf) {
        As[buf][kq + 0][row] = ra.x;  As[buf][kq + 1][row] = ra.y;
        As[buf][kq + 2][row] = ra.z;  As[buf][kq + 3][row] = ra.w;
        Bs[buf][kq + 0][row] = rb0.x; Bs[buf][kq + 1][row] = rb0.y;
        Bs[buf][kq + 2][row] = rb0.z; Bs[buf][kq + 3][row] = rb0.w;
        Bs[buf][kq + 0][row + 64] = rb1.x; Bs[buf][kq + 1][row + 64] = rb1.y;
        Bs[buf][kq + 2][row + 64] = rb1.z; Bs[buf][kq + 3][row + 64] = rb1.w;
    };

    LD(0); ST(0);
    __syncthreads();
    const int KT = K >> 4;   // 64
    int cur = 0;
    for (int kt = 0; kt < KT; ++kt) {
        if (kt + 1 < KT) LD(kt + 1);

        float4 af[2]; ulonglong2 bl[2], bh[2];
        af[0] = *(const float4*)&As[cur][0][ty4];
        bl[0] = *(const ulonglong2*)&Bs[cur][0][tx8];
        bh[0] = *(const ulonglong2*)&Bs[cur][0][tx8 + 4];
#pragma unroll
        for (int k = 0; k < 16; ++k) {
            const int cu = k & 1, nx = cu ^ 1;
            if (k < 15) {
                af[nx] = *(const float4*)&As[cur][k + 1][ty4];
                bl[nx] = *(const ulonglong2*)&Bs[cur][k + 1][tx8];
                bh[nx] = *(const ulonglong2*)&Bs[cur][k + 1][tx8 + 4];
            }
            unsigned long long ad[4] = {dup2(af[cu].x), dup2(af[cu].y), dup2(af[cu].z), dup2(af[cu].w)};
            unsigned long long bd[4] = {bl[cu].x, bl[cu].y, bh[cu].x, bh[cu].y};
#pragma unroll
            for (int i = 0; i < 4; i++)
#pragma unroll
                for (int p = 0; p < 4; p++)
                    ffma2(acc[i][p], ad[i], bd[p]);
        }
        if (kt + 1 < KT) ST(cur ^ 1);
        __syncthreads();
        cur ^= 1;
    }

    // epilogue: + b_out + gumbel, block argmax, global atomic merge
    if (tid < 64) rowmax[tid] = 0ull;
    if (tid < 128) {
        int n = bn + tid;
        bo[tid] = (n < N) ? bout[n] : 0.f;
    }
    __syncthreads();

#pragma unroll
    for (int i = 0; i < 4; i++) {
        int m = bm + ty4 + i;
        const float* grow = gumbel + ((size_t)step * NB + m) * (size_t)NV + bn;
        unsigned long long best = 0ull;
#pragma unroll
        for (int p = 0; p < 4; p++) {
            int nl = tx8 + 2 * p;
            int n = bn + nl;
            if (n + 1 < N) {
                float2 g = *(const float2*)(grow + nl);
                float v0 = lo32(acc[i][p]) + bo[nl] + g.x;
                float v1 = hi32(acc[i][p]) + bo[nl + 1] + g.y;
                unsigned long long p0 = packmax(v0, n);
                unsigned long long p1 = packmax(v1, n + 1);
                unsigned long long pm = p0 > p1 ? p0 : p1;
                if (pm > best) best = pm;
            } else if (n < N) {
                float v0 = lo32(acc[i][p]) + bo[nl] + grow[nl];
                unsigned long long p0 = packmax(v0, n);
                if (p0 > best) best = p0;
            }
        }
        atomicMax(&rowmax[ty4 + i], best);
    }
    __syncthreads();
    if (tid < 64 && rowmax[tid])
        atomicMax(&g_amax[bm + tid], rowmax[tid]);
}

// ---------------- finalize step: decode argmax, write one-hot, gather next x ----------------
__global__ void finalize_kernel(const float* __restrict__ emb, float* __restrict__ out, int s) {
    int b = blockIdx.x;
    __shared__ int stok;
    if (threadIdx.x == 0) {
        unsigned long long p = g_amax[b];
        int t = (int)(0xFFFFFFFFu - (unsigned)(p & 0xFFFFFFFFull));
        stok = t;
        g_tok[s * NB + b] = t;
        g_amax[b] = 0ull;
        out[((size_t)b * NS + s) * NV + t] = 1.0f;
    }
    __syncthreads();
    int t = stok;
    for (int k = threadIdx.x; k < DEMB; k += 128)
        g_x[b * DEMB + k] = fmaxf(emb[(size_t)t * DEMB + k], 0.f);
}

// ---------------- msg_lens: last EOS index + 1, else S ----------------
__global__ void lens_kernel(float* __restrict__ out, int out_size) {
    int b = threadIdx.x;
    int len = NS;
    for (int s = NS - 1; s >= 0; --s) {
        if (g_tok[s * NB + b] == EOS_TOK) { len = s + 1; break; }
    }
    if (out_size >= NB * NS * NV + NB)
        out[(size_t)NB * NS * NV + b] = (float)len;
}

// ---------------- launch ----------------
extern "C" void kernel_launch(void* const* d_in, const int* in_sizes, int n_in,
                              void* d_out, int out_size)
{
    const float* image = (const float*)d_in[0];
    const float* W_b   = (const float*)d_in[1];
    const float* emb   = (const float*)d_in[2];
    const float* w_ih  = (const float*)d_in[3];
    const float* w_hh  = (const float*)d_in[4];
    const float* b_ih  = (const float*)d_in[5];
    const float* b_hh  = (const float*)d_in[6];
    const float* W_out = (const float*)d_in[7];
    const float* b_out = (const float*)d_in[8];
    const float* gum   = (const float*)d_in[9];
    float* out = (float*)d_out;

    float *p_h0, *p_h1, *p_x, *p_G1, *p_G2, *p_WbT;
    cudaGetSymbolAddress((void**)&p_h0,  g_h0);
    cudaGetSymbolAddress((void**)&p_h1,  g_h1);
    cudaGetSymbolAddress((void**)&p_x,   g_x);
    cudaGetSymbolAddress((void**)&p_G1,  g_G1);
    cudaGetSymbolAddress((void**)&p_G2,  g_G2);
    cudaGetSymbolAddress((void**)&p_WbT, g_WbT);

    // zero the one-hot region
    long long n4 = (long long)NB * NS * NV / 4;
    zero_out<<<(unsigned)((n4 + 255) / 256), 256>>>((float4*)out, n4);

    // one-time prep
    transpose_wb<<<dim3(DIMG / 32, DHID / 32), dim3(32, 8)>>>(W_b);
    init_kernel<<<NB, 128>>>(emb);

    // h0 = image @ W_b
    gemm32_dual<<<dim3(DHID / 128, NB / 32, 1), 256>>>(
        image, p_WbT, p_h0, DIMG,
        image, p_WbT, p_h0, DIMG,
        DHID);

    for (int s = 0; s < NS; ++s) {
        const float* hc = (s & 1) ? p_h1 : p_h0;
        float*       hn = (s & 1) ? p_h0 : p_h1;
        // fused gate GEMMs: z=0 -> G1 = x @ w_ih^T (K=512); z=1 -> G2 = h @ w_hh^T (K=1024)
        gemm32_dual<<<dim3(3 * DHID / 128, NB / 32, 2), 256>>>(
            p_x, w_ih, p_G1, DEMB,
            hc,  w_hh, p_G2, DHID,
            3 * DHID);
        gru_elem<<<(NB * DHID / 4) / 256, 256>>>(b_ih, b_hh, hc, hn);
        gemm_logits<<<dim3((NV + 127) / 128, NB / 64), 256>>>(hn, W_out, b_out, gum, s);
        finalize_kernel<<<NB, 128>>>(emb, out, s);
    }

    lens_kernel<<<1, 256>>>(out, out_size);
}

// round 6
// speedup vs baseline: 1.5470x; 1.5470x over previous
#include <cuda_runtime.h>
#include <cstdint>

#define NB 256
#define NS 32
#define NV 10000
#define DEMB 512
#define DHID 1024
#define DIMG 2048
#define BOS_TOK 1
#define EOS_TOK 2

// ---------------- device scratch (static, no allocations) ----------------
__device__ float g_h0[NB * DHID];
__device__ float g_h1[NB * DHID];
__device__ float g_x [NB * DEMB];          // relu(emb[token]) for current step
__device__ float g_G1[NB * 3 * DHID];      // x @ w_ih^T
__device__ float g_G2[NB * 3 * DHID];      // h @ w_hh^T
__device__ float g_WbT[DHID * DIMG];       // W_b transposed -> [DHID][DIMG]
__device__ unsigned long long g_amax[NB];  // packed (value,index) argmax per row
__device__ int g_tok[NS * NB];

// order-preserving (float,index) pack; max => max value, ties => smallest index
__device__ __forceinline__ unsigned long long packmax(float v, int idx) {
    unsigned int b = __float_as_uint(v);
    b = (b & 0x80000000u) ? ~b : (b | 0x80000000u);
    return ((unsigned long long)b << 32) | (unsigned long long)(0xFFFFFFFFu - (unsigned)idx);
}

// ---------------- tf32 helpers ----------------
__device__ __forceinline__ void split_tf32(float a, float& hi, float& lo) {
    unsigned int h, l;
    asm("cvt.rna.tf32.f32 %0, %1;" : "=r"(h) : "f"(a));
    float ah = __uint_as_float(h);
    float al = a - ah;
    asm("cvt.rna.tf32.f32 %0, %1;" : "=r"(l) : "f"(al));
    hi = __uint_as_float(h);
    lo = __uint_as_float(l);
}

__device__ __forceinline__ void mma_tf32(float4& d, const unsigned int a[4], const unsigned int b[2]) {
    asm volatile(
        "mma.sync.aligned.m16n8k8.row.col.f32.tf32.tf32.f32 "
        "{%0,%1,%2,%3}, {%4,%5,%6,%7}, {%8,%9}, {%0,%1,%2,%3};"
        : "+f"(d.x), "+f"(d.y), "+f"(d.z), "+f"(d.w)
        : "r"(a[0]), "r"(a[1]), "r"(a[2]), "r"(a[3]), "r"(b[0]), "r"(b[1]));
}

// ---------------- W_b transpose: [DIMG][DHID] -> [DHID][DIMG] ----------------
__global__ void transpose_wb(const float* __restrict__ Wb) {
    __shared__ float t[32][33];
    int k0 = blockIdx.x * 32;
    int n0 = blockIdx.y * 32;
    for (int i = threadIdx.y; i < 32; i += 8)
        t[i][threadIdx.x] = Wb[(size_t)(k0 + i) * DHID + n0 + threadIdx.x];
    __syncthreads();
    for (int i = threadIdx.y; i < 32; i += 8)
        g_WbT[(size_t)(n0 + i) * DIMG + k0 + threadIdx.x] = t[threadIdx.x][i];
}

// ---------------- zero the one-hot output ----------------
__global__ void zero_out(float4* o, long long n4) {
    long long i = (long long)blockIdx.x * blockDim.x + threadIdx.x;
    if (i < n4) o[i] = make_float4(0.f, 0.f, 0.f, 0.f);
}

// ---------------- init: x0 = relu(emb[BOS]), amax reset ----------------
__global__ void init_kernel(const float* __restrict__ emb) {
    int b = blockIdx.x;
    if (threadIdx.x == 0) g_amax[b] = 0ull;
    for (int k = threadIdx.x; k < DEMB; k += 128)
        g_x[b * DEMB + k] = fmaxf(emb[(size_t)BOS_TOK * DEMB + k], 0.f);
}

// =====================================================================
// 3xTF32 tensor-core GEMM:  C[M,N] = A[M,K] * B[N,K]^T   (fp32-faithful)
// CTA tile 64x128, 8 warps, warp tile 32x32 (2x4 m16n8k8 frags).
// EPI=0: store C.  EPI=1: fused +bias +gumbel + packed argmax.
// NG: guard B rows / output cols against N.
// =====================================================================
template<int EPI, bool NG>
__global__ __launch_bounds__(256, 2)
void mma_gemm(const float* __restrict__ A0, const float* __restrict__ B0, float* __restrict__ C0, int K0,
              const float* __restrict__ A1, const float* __restrict__ B1, float* __restrict__ C1, int K1,
              int N,
              const float* __restrict__ bout, const float* __restrict__ gumbel, int step)
{
    const float* A; const float* B; float* C; int K;
    if (blockIdx.z == 0) { A = A0; B = B0; C = C0; K = K0; }
    else                 { A = A1; B = B1; C = C1; K = K1; }

    // smem: AsH/AsL [2][16][68], BsH/BsL [2][16][132]  (floats)
    __shared__ float sm[12800];
    float* AsH = sm;
    float* AsL = sm + 2176;
    float* BsH = sm + 4352;
    float* BsL = sm + 8576;
    __shared__ unsigned long long rowmax[64];

    const int tid  = threadIdx.x;
    const int lane = tid & 31;
    const int wid  = tid >> 5;
    const int wm = wid >> 2;            // 0..1
    const int wn = wid & 3;             // 0..3
    const int gid = lane >> 2;          // 0..7
    const int tig = lane & 3;           // 0..3
    const int bm = blockIdx.y * 64;
    const int bn = blockIdx.x * 128;

    // stage-load indices
    const int arow = tid >> 2;          // 0..63
    const int akq  = (tid & 3) * 4;     // 0,4,8,12
    const int brow = tid >> 1;          // 0..127
    const int bkq  = (tid & 1) * 8;     // 0 or 8

    const float* Ag = A + (size_t)(bm + arow) * K + akq;
    const bool bok = (!NG) || (bn + brow) < N;
    const float* Bg = B + (size_t)(bn + brow) * K + bkq;

    float4 acc[2][4];
#pragma unroll
    for (int i = 0; i < 2; i++)
#pragma unroll
        for (int j = 0; j < 4; j++) acc[i][j] = make_float4(0.f, 0.f, 0.f, 0.f);

    float4 ra, rb0, rb1;
    const float4 f4z = make_float4(0.f, 0.f, 0.f, 0.f);
    auto LD = [&](int kt) {
        ra  = *(const float4*)(Ag + kt * 16);
        rb0 = bok ? *(const float4*)(Bg + kt * 16)     : f4z;
        rb1 = bok ? *(const float4*)(Bg + kt * 16 + 4) : f4z;
    };
    auto ST = [&](int buf) {
        const int ab = buf * 1088;
        const int bb = buf * 2112;
        float av[4] = {ra.x, ra.y, ra.z, ra.w};
#pragma unroll
        for (int i = 0; i < 4; i++) {
            float h, l; split_tf32(av[i], h, l);
            AsH[ab + (akq + i) * 68 + arow] = h;
            AsL[ab + (akq + i) * 68 + arow] = l;
        }
        float bv[8] = {rb0.x, rb0.y, rb0.z, rb0.w, rb1.x, rb1.y, rb1.z, rb1.w};
#pragma unroll
        for (int i = 0; i < 8; i++) {
            float h, l; split_tf32(bv[i], h, l);
            BsH[bb + (bkq + i) * 132 + brow] = h;
            BsL[bb + (bkq + i) * 132 + brow] = l;
        }
    };

    LD(0); ST(0);
    if (EPI == 1 && tid < 64) rowmax[tid] = 0ull;
    __syncthreads();

    const int KT = K >> 4;
    int cur = 0;
    for (int kt = 0; kt < KT; ++kt) {
        if (kt + 1 < KT) LD(kt + 1);

        const int ab = cur * 1088;
        const int bb = cur * 2112;
#pragma unroll
        for (int k8 = 0; k8 < 2; ++k8) {
            const int kb = k8 * 8;
            unsigned int aH[2][4], aL[2][4], bH[4][2], bL[4][2];
#pragma unroll
            for (int mf = 0; mf < 2; ++mf) {
                const int m = wm * 32 + mf * 16 + gid;
                const int r0 = ab + (kb + tig) * 68;
                const int r1 = ab + (kb + tig + 4) * 68;
                aH[mf][0] = __float_as_uint(AsH[r0 + m]);
                aH[mf][1] = __float_as_uint(AsH[r0 + m + 8]);
                aH[mf][2] = __float_as_uint(AsH[r1 + m]);
                aH[mf][3] = __float_as_uint(AsH[r1 + m + 8]);
                aL[mf][0] = __float_as_uint(AsL[r0 + m]);
                aL[mf][1] = __float_as_uint(AsL[r0 + m + 8]);
                aL[mf][2] = __float_as_uint(AsL[r1 + m]);
                aL[mf][3] = __float_as_uint(AsL[r1 + m + 8]);
            }
#pragma unroll
            for (int nf = 0; nf < 4; ++nf) {
                const int n = wn * 32 + nf * 8 + gid;
                const int r0 = bb + (kb + tig) * 132;
                const int r1 = bb + (kb + tig + 4) * 132;
                bH[nf][0] = __float_as_uint(BsH[r0 + n]);
                bH[nf][1] = __float_as_uint(BsH[r1 + n]);
                bL[nf][0] = __float_as_uint(BsL[r0 + n]);
                bL[nf][1] = __float_as_uint(BsL[r1 + n]);
            }
            // 3xTF32: small terms first, big last; 8 independent accs between reuses
#pragma unroll
            for (int mf = 0; mf < 2; ++mf)
#pragma unroll
                for (int nf = 0; nf < 4; ++nf)
                    mma_tf32(acc[mf][nf], aL[mf], bH[nf]);
#pragma unroll
            for (int mf = 0; mf < 2; ++mf)
#pragma unroll
                for (int nf = 0; nf < 4; ++nf)
                    mma_tf32(acc[mf][nf], aH[mf], bL[nf]);
#pragma unroll
            for (int mf = 0; mf < 2; ++mf)
#pragma unroll
                for (int nf = 0; nf < 4; ++nf)
                    mma_tf32(acc[mf][nf], aH[mf], bH[nf]);
        }

        if (kt + 1 < KT) ST(cur ^ 1);
        __syncthreads();
        cur ^= 1;
    }

    if (EPI == 0) {
        // plain store
#pragma unroll
        for (int mf = 0; mf < 2; ++mf) {
            const int row = bm + wm * 32 + mf * 16 + gid;
#pragma unroll
            for (int nf = 0; nf < 4; ++nf) {
                const int col = bn + wn * 32 + nf * 8 + 2 * tig;
                float4 v = acc[mf][nf];
                *(float2*)(C + (size_t)row * N + col)       = make_float2(v.x, v.y);
                *(float2*)(C + (size_t)(row + 8) * N + col) = make_float2(v.z, v.w);
            }
        }
    } else {
        // fused +bias +gumbel + packed argmax
#pragma unroll
        for (int mf = 0; mf < 2; ++mf) {
            const int lm0 = wm * 32 + mf * 16 + gid;
            const int m0 = bm + lm0;
            unsigned long long best0 = 0ull, best1 = 0ull;
#pragma unroll
            for (int nf = 0; nf < 4; ++nf) {
                const int n = bn + wn * 32 + nf * 8 + 2 * tig;
                if (!NG || n < N) {      // N even, n even => pair fully in range
                    float2 bo = *(const float2*)(bout + n);
                    const float* g0 = gumbel + ((size_t)step * NB + m0) * (size_t)NV + n;
                    float2 ga = *(const float2*)g0;
                    float2 gb = *(const float2*)(g0 + (size_t)8 * NV);
                    float4 v = acc[mf][nf];
                    unsigned long long p;
                    p = packmax(v.x + bo.x + ga.x, n);     if (p > best0) best0 = p;
                    p = packmax(v.y + bo.y + ga.y, n + 1); if (p > best0) best0 = p;
                    p = packmax(v.z + bo.x + gb.x, n);     if (p > best1) best1 = p;
                    p = packmax(v.w + bo.y + gb.y, n + 1); if (p > best1) best1 = p;
                }
            }
            if (best0) atomicMax(&rowmax[lm0], best0);
            if (best1) atomicMax(&rowmax[lm0 + 8], best1);
        }
        __syncthreads();
        if (tid < 64 && rowmax[tid])
            atomicMax(&g_amax[bm + tid], rowmax[tid]);
    }
}

// ---------------- GRU elementwise (float4): h_new from G1, G2, biases, h_old ----------------
__global__ void gru_elem(const float* __restrict__ b_ih, const float* __restrict__ b_hh,
                         const float* __restrict__ hOld, float* __restrict__ hNew)
{
    int idx = blockIdx.x * blockDim.x + threadIdx.x;   // NB*DHID/4
    int m = idx >> 8;                 // DHID/4 = 256 float4 per row
    int j = (idx & 255) * 4;
    const float* G1 = g_G1 + (size_t)m * (3 * DHID);
    const float* G2 = g_G2 + (size_t)m * (3 * DHID);

    float4 ir = *(const float4*)(G1 + j);
    float4 iz = *(const float4*)(G1 + DHID + j);
    float4 in_ = *(const float4*)(G1 + 2 * DHID + j);
    float4 hr = *(const float4*)(G2 + j);
    float4 hz = *(const float4*)(G2 + DHID + j);
    float4 hn = *(const float4*)(G2 + 2 * DHID + j);
    float4 bir = *(const float4*)(b_ih + j);
    float4 biz = *(const float4*)(b_ih + DHID + j);
    float4 bin = *(const float4*)(b_ih + 2 * DHID + j);
    float4 bhr = *(const float4*)(b_hh + j);
    float4 bhz = *(const float4*)(b_hh + DHID + j);
    float4 bhn = *(const float4*)(b_hh + 2 * DHID + j);
    float4 ho = *(const float4*)(hOld + (size_t)m * DHID + j);

    float4 res;
#define GRU1(c) { \
        float r = 1.f / (1.f + expf(-((ir.c + bir.c) + (hr.c + bhr.c)))); \
        float z = 1.f / (1.f + expf(-((iz.c + biz.c) + (hz.c + bhz.c)))); \
        float n = tanhf((in_.c + bin.c) + r * (hn.c + bhn.c)); \
        res.c = (1.f - z) * n + z * ho.c; }
    GRU1(x) GRU1(y) GRU1(z) GRU1(w)
#undef GRU1
    *(float4*)(hNew + (size_t)m * DHID + j) = res;
}

// ---------------- finalize step: decode argmax, write one-hot, gather next x ----------------
__global__ void finalize_kernel(const float* __restrict__ emb, float* __restrict__ out, int s) {
    int b = blockIdx.x;
    __shared__ int stok;
    if (threadIdx.x == 0) {
        unsigned long long p = g_amax[b];
        int t = (int)(0xFFFFFFFFu - (unsigned)(p & 0xFFFFFFFFull));
        stok = t;
        g_tok[s * NB + b] = t;
        g_amax[b] = 0ull;
        out[((size_t)b * NS + s) * NV + t] = 1.0f;
    }
    __syncthreads();
    int t = stok;
    for (int k = threadIdx.x; k < DEMB; k += 128)
        g_x[b * DEMB + k] = fmaxf(emb[(size_t)t * DEMB + k], 0.f);
}

// ---------------- msg_lens: last EOS index + 1, else S ----------------
__global__ void lens_kernel(float* __restrict__ out, int out_size) {
    int b = threadIdx.x;
    int len = NS;
    for (int s = NS - 1; s >= 0; --s) {
        if (g_tok[s * NB + b] == EOS_TOK) { len = s + 1; break; }
    }
    if (out_size >= NB * NS * NV + NB)
        out[(size_t)NB * NS * NV + b] = (float)len;
}

// ---------------- launch ----------------
extern "C" void kernel_launch(void* const* d_in, const int* in_sizes, int n_in,
                              void* d_out, int out_size)
{
    const float* image = (const float*)d_in[0];
    const float* W_b   = (const float*)d_in[1];
    const float* emb   = (const float*)d_in[2];
    const float* w_ih  = (const float*)d_in[3];
    const float* w_hh  = (const float*)d_in[4];
    const float* b_ih  = (const float*)d_in[5];
    const float* b_hh  = (const float*)d_in[6];
    const float* W_out = (const float*)d_in[7];
    const float* b_out = (const float*)d_in[8];
    const float* gum   = (const float*)d_in[9];
    float* out = (float*)d_out;

    float *p_h0, *p_h1, *p_x, *p_G1, *p_G2, *p_WbT;
    cudaGetSymbolAddress((void**)&p_h0,  g_h0);
    cudaGetSymbolAddress((void**)&p_h1,  g_h1);
    cudaGetSymbolAddress((void**)&p_x,   g_x);
    cudaGetSymbolAddress((void**)&p_G1,  g_G1);
    cudaGetSymbolAddress((void**)&p_G2,  g_G2);
    cudaGetSymbolAddress((void**)&p_WbT, g_WbT);

    // zero the one-hot region
    long long n4 = (long long)NB * NS * NV / 4;
    zero_out<<<(unsigned)((n4 + 255) / 256), 256>>>((float4*)out, n4);

    // one-time prep
    transpose_wb<<<dim3(DIMG / 32, DHID / 32), dim3(32, 8)>>>(W_b);
    init_kernel<<<NB, 128>>>(emb);

    // h0 = image @ W_b
    mma_gemm<0, false><<<dim3(DHID / 128, NB / 64, 1), 256>>>(
        image, p_WbT, p_h0, DIMG,
        image, p_WbT, p_h0, DIMG,
        DHID, nullptr, nullptr, 0);

    for (int s = 0; s < NS; ++s) {
        const float* hc = (s & 1) ? p_h1 : p_h0;
        float*       hn = (s & 1) ? p_h0 : p_h1;
        // fused gate GEMMs: z=0 -> G1 = x @ w_ih^T (K=512); z=1 -> G2 = h @ w_hh^T (K=1024)
        mma_gemm<0, false><<<dim3(3 * DHID / 128, NB / 64, 2), 256>>>(
            p_x, w_ih, p_G1, DEMB,
            hc,  w_hh, p_G2, DHID,
            3 * DHID, nullptr, nullptr, 0);
        gru_elem<<<(NB * DHID / 4) / 256, 256>>>(b_ih, b_hh, hc, hn);
        // logits + bias + gumbel + argmax
        mma_gemm<1, true><<<dim3((NV + 127) / 128, NB / 64, 1), 256>>>(
            hn, W_out, nullptr, DHID,
            hn, W_out, nullptr, DHID,
            NV, b_out, gum, s);
        finalize_kernel<<<NB, 128>>>(emb, out, s);
    }

    lens_kernel<<<1, 256>>>(out, out_size);
}

// round 7
// speedup vs baseline: 2.2688x; 1.4666x over previous
#include <cuda_runtime.h>
#include <cstdint>

#define NB 256
#define NS 32
#define NV 10000
#define DEMB 512
#define DHID 1024
#define DIMG 2048
#define BOS_TOK 1
#define EOS_TOK 2

// ---------------- device scratch (static, no allocations) ----------------
__device__ float g_h0[NB * DHID];
__device__ float g_h1[NB * DHID];
__device__ float g_x [NB * DEMB];          // relu(emb[token]) for current step
__device__ float g_G1[NB * 3 * DHID];      // x @ w_ih^T
__device__ float g_G2[NB * 3 * DHID];      // h @ w_hh^T
__device__ float g_WbT[DHID * DIMG];       // W_b transposed -> [DHID][DIMG]
__device__ unsigned long long g_amax[NB];  // packed (value,index) argmax per row
__device__ int g_tok[NS * NB];

// order-preserving (float,index) pack; max => max value, ties => smallest index
__device__ __forceinline__ unsigned long long packmax(float v, int idx) {
    unsigned int b = __float_as_uint(v);
    b = (b & 0x80000000u) ? ~b : (b | 0x80000000u);
    return ((unsigned long long)b << 32) | (unsigned long long)(0xFFFFFFFFu - (unsigned)idx);
}

// ---------------- tf32 helpers ----------------
__device__ __forceinline__ void split_tf32(float a, float& hi, float& lo) {
    unsigned int h, l;
    asm("cvt.rna.tf32.f32 %0, %1;" : "=r"(h) : "f"(a));
    float ah = __uint_as_float(h);
    float al = a - ah;
    asm("cvt.rna.tf32.f32 %0, %1;" : "=r"(l) : "f"(al));
    hi = __uint_as_float(h);
    lo = __uint_as_float(l);
}

__device__ __forceinline__ void mma_tf32(float4& d, const unsigned int* a, const unsigned int* b) {
    asm volatile(
        "mma.sync.aligned.m16n8k8.row.col.f32.tf32.tf32.f32 "
        "{%0,%1,%2,%3}, {%4,%5,%6,%7}, {%8,%9}, {%0,%1,%2,%3};"
        : "+f"(d.x), "+f"(d.y), "+f"(d.z), "+f"(d.w)
        : "r"(a[0]), "r"(a[1]), "r"(a[2]), "r"(a[3]), "r"(b[0]), "r"(b[1]));
}

__device__ __forceinline__ void ldsm4(unsigned& r0, unsigned& r1, unsigned& r2, unsigned& r3,
                                      unsigned addr) {
    asm volatile("ldmatrix.sync.aligned.m8n8.x4.shared.b16 {%0,%1,%2,%3}, [%4];"
                 : "=r"(r0), "=r"(r1), "=r"(r2), "=r"(r3) : "r"(addr));
}

__device__ __forceinline__ void sts128(unsigned addr, float a, float b, float c, float d) {
    asm volatile("st.shared.v4.f32 [%0], {%1,%2,%3,%4};"
                 :: "r"(addr), "f"(a), "f"(b), "f"(c), "f"(d));
}

// ---------------- W_b transpose: [DIMG][DHID] -> [DHID][DIMG] ----------------
__global__ void transpose_wb(const float* __restrict__ Wb) {
    __shared__ float t[32][33];
    int k0 = blockIdx.x * 32;
    int n0 = blockIdx.y * 32;
    for (int i = threadIdx.y; i < 32; i += 8)
        t[i][threadIdx.x] = Wb[(size_t)(k0 + i) * DHID + n0 + threadIdx.x];
    __syncthreads();
    for (int i = threadIdx.y; i < 32; i += 8)
        g_WbT[(size_t)(n0 + i) * DIMG + k0 + threadIdx.x] = t[threadIdx.x][i];
}

// ---------------- zero the one-hot output ----------------
__global__ void zero_out(float4* o, long long n4) {
    long long i = (long long)blockIdx.x * blockDim.x + threadIdx.x;
    if (i < n4) o[i] = make_float4(0.f, 0.f, 0.f, 0.f);
}

// ---------------- init: x0 = relu(emb[BOS]), amax reset ----------------
__global__ void init_kernel(const float* __restrict__ emb) {
    int b = blockIdx.x;
    if (threadIdx.x == 0) g_amax[b] = 0ull;
    for (int k = threadIdx.x; k < DEMB; k += 128)
        g_x[b * DEMB + k] = fmaxf(emb[(size_t)BOS_TOK * DEMB + k], 0.f);
}

// =====================================================================
// 3xTF32 tensor-core GEMM:  C[M,N] = A[M,K] * B[N,K]^T   (fp32-faithful)
// CTA tile 64x128, 8 warps, warp tile 32x32 (2x4 m16n8k8 frags).
// Smem: XOR-swizzled rows of 8x16B chunks (H/L interleaved per k-quad),
// fragments loaded via ldmatrix.x4 (conflict-free), staging via STS.128.
//   A stage: 64 rows x 128B  (8 KB)  x2 stages = 16 KB  @ sm[0]
//   B stage: 128 rows x 128B (16 KB) x2 stages = 32 KB  @ sm[4096]
// EPI=0: store C.  EPI=1: fused +bias +gumbel + packed argmax.
// =====================================================================
template<int EPI, bool NG>
__global__ __launch_bounds__(256, 2)
void mma_gemm(const float* __restrict__ A0, const float* __restrict__ B0, float* __restrict__ C0, int K0,
              const float* __restrict__ A1, const float* __restrict__ B1, float* __restrict__ C1, int K1,
              int N,
              const float* __restrict__ bout, const float* __restrict__ gumbel, int step)
{
    const float* A; const float* B; float* C; int K;
    if (blockIdx.z == 0) { A = A0; B = B0; C = C0; K = K0; }
    else                 { A = A1; B = B1; C = C1; K = K1; }

    __shared__ __align__(128) float sm[12288];   // 48 KB exactly
    const unsigned sbase = (unsigned)__cvta_generic_to_shared(sm);

    const int tid  = threadIdx.x;
    const int lane = tid & 31;
    const int wid  = tid >> 5;
    const int wm = wid >> 2;            // 0..1
    const int wn = wid & 3;             // 0..3
    const int gid = lane >> 2;          // 0..7
    const int tig = lane & 3;           // 0..3
    const int bm = blockIdx.y * 64;
    const int bn = blockIdx.x * 128;

    // ---- staging indices ----
    const int arow = tid >> 2;          // 0..63
    const int akq  = (tid & 3) * 4;     // 0,4,8,12
    const int brow = tid >> 1;          // 0..127
    const int bkq  = (tid & 1) * 8;     // 0 or 8

    const float* Ag = A + (size_t)(bm + arow) * K + akq;
    const bool bok = (!NG) || (bn + brow) < N;
    const float* Bg = B + (size_t)(bn + brow) * K + bkq;

    // staging store base offsets (chunk-swizzled); L/other chunks via XOR
    const unsigned awH = (unsigned)(arow * 128 + ((((akq >> 2) * 2) ^ (arow & 7)) * 16));
    const unsigned bwH = (unsigned)(brow * 128 + ((((bkq >> 2) * 2) ^ (brow & 7)) * 16));

    // ---- ldmatrix per-lane offsets (k8 = 0); XOR 64 selects k8 = 1 ----
    const int swl = lane & 7;
    unsigned aOff[2][2], bOff[2][2];
    {
        const int am  = wm * 32 + (lane & 15);
        const int cba = ((lane >> 4) & 1) * 2;
#pragma unroll
        for (int mf = 0; mf < 2; ++mf)
#pragma unroll
            for (int hl = 0; hl < 2; ++hl)
                aOff[mf][hl] = (unsigned)((am + mf * 16) * 128 + (((cba + hl) ^ swl) * 16));
        const int nr  = wn * 32 + ((lane >> 4) & 1) * 8 + (lane & 7);
        const int cbb = ((lane >> 3) & 1) * 2;
#pragma unroll
        for (int nfp = 0; nfp < 2; ++nfp)
#pragma unroll
            for (int hl = 0; hl < 2; ++hl)
                bOff[nfp][hl] = (unsigned)((nr + nfp * 16) * 128 + (((cbb + hl) ^ swl) * 16));
    }

    float4 acc[2][4];
#pragma unroll
    for (int i = 0; i < 2; i++)
#pragma unroll
        for (int j = 0; j < 4; j++) acc[i][j] = make_float4(0.f, 0.f, 0.f, 0.f);

    float4 ra, rb0, rb1;
    const float4 f4z = make_float4(0.f, 0.f, 0.f, 0.f);
    auto LD = [&](int kt) {
        ra  = *(const float4*)(Ag + kt * 16);
        rb0 = bok ? *(const float4*)(Bg + kt * 16)     : f4z;
        rb1 = bok ? *(const float4*)(Bg + kt * 16 + 4) : f4z;
    };
    auto ST = [&](int buf) {
        const unsigned ab = sbase + (unsigned)buf * 8192u;
        const unsigned bb = sbase + 16384u + (unsigned)buf * 16384u;
        float h0, l0, h1, l1, h2, l2, h3, l3;
        split_tf32(ra.x, h0, l0); split_tf32(ra.y, h1, l1);
        split_tf32(ra.z, h2, l2); split_tf32(ra.w, h3, l3);
        unsigned pa = ab + awH;
        sts128(pa,       h0, h1, h2, h3);
        sts128(pa ^ 16u, l0, l1, l2, l3);
        split_tf32(rb0.x, h0, l0); split_tf32(rb0.y, h1, l1);
        split_tf32(rb0.z, h2, l2); split_tf32(rb0.w, h3, l3);
        unsigned pb = bb + bwH;
        sts128(pb,       h0, h1, h2, h3);
        sts128(pb ^ 16u, l0, l1, l2, l3);
        split_tf32(rb1.x, h0, l0); split_tf32(rb1.y, h1, l1);
        split_tf32(rb1.z, h2, l2); split_tf32(rb1.w, h3, l3);
        sts128(pb ^ 32u, h0, h1, h2, h3);
        sts128(pb ^ 48u, l0, l1, l2, l3);
    };

    LD(0); ST(0);
    __syncthreads();

    const int KT = K >> 4;
    int cur = 0;
    for (int kt = 0; kt < KT; ++kt) {
        if (kt + 1 < KT) LD(kt + 1);

        const unsigned aBase = sbase + (unsigned)cur * 8192u;
        const unsigned bBase = sbase + 16384u + (unsigned)cur * 16384u;
#pragma unroll
        for (int k8 = 0; k8 < 2; ++k8) {
            const unsigned kx = (unsigned)k8 * 64u;
            unsigned aH[2][4], aL[2][4], bH[4][2], bL[4][2];
#pragma unroll
            for (int mf = 0; mf < 2; ++mf) {
                ldsm4(aH[mf][0], aH[mf][1], aH[mf][2], aH[mf][3], aBase + (aOff[mf][0] ^ kx));
                ldsm4(aL[mf][0], aL[mf][1], aL[mf][2], aL[mf][3], aBase + (aOff[mf][1] ^ kx));
            }
#pragma unroll
            for (int nfp = 0; nfp < 2; ++nfp) {
                unsigned r0, r1, r2, r3;
                ldsm4(r0, r1, r2, r3, bBase + (bOff[nfp][0] ^ kx));
                bH[2 * nfp][0] = r0; bH[2 * nfp][1] = r1;
                bH[2 * nfp + 1][0] = r2; bH[2 * nfp + 1][1] = r3;
                ldsm4(r0, r1, r2, r3, bBase + (bOff[nfp][1] ^ kx));
                bL[2 * nfp][0] = r0; bL[2 * nfp][1] = r1;
                bL[2 * nfp + 1][0] = r2; bL[2 * nfp + 1][1] = r3;
            }
            // 3xTF32: small terms first, big last; 8 independent accs between reuses
#pragma unroll
            for (int mf = 0; mf < 2; ++mf)
#pragma unroll
                for (int nf = 0; nf < 4; ++nf)
                    mma_tf32(acc[mf][nf], aL[mf], bH[nf]);
#pragma unroll
            for (int mf = 0; mf < 2; ++mf)
#pragma unroll
                for (int nf = 0; nf < 4; ++nf)
                    mma_tf32(acc[mf][nf], aH[mf], bL[nf]);
#pragma unroll
            for (int mf = 0; mf < 2; ++mf)
#pragma unroll
                for (int nf = 0; nf < 4; ++nf)
                    mma_tf32(acc[mf][nf], aH[mf], bH[nf]);
        }

        if (kt + 1 < KT) ST(cur ^ 1);
        __syncthreads();
        cur ^= 1;
    }

    if (EPI == 0) {
        // plain store
#pragma unroll
        for (int mf = 0; mf < 2; ++mf) {
            const int row = bm + wm * 32 + mf * 16 + gid;
#pragma unroll
            for (int nf = 0; nf < 4; ++nf) {
                const int col = bn + wn * 32 + nf * 8 + 2 * tig;
                float4 v = acc[mf][nf];
                *(float2*)(C + (size_t)row * N + col)       = make_float2(v.x, v.y);
                *(float2*)(C + (size_t)(row + 8) * N + col) = make_float2(v.z, v.w);
            }
        }
    } else {
        // fused +bias +gumbel + packed argmax (rowmax aliased onto smem, post-loop)
        unsigned long long* rowmax = (unsigned long long*)sm;
        if (tid < 64) rowmax[tid] = 0ull;
        __syncthreads();
#pragma unroll
        for (int mf = 0; mf < 2; ++mf) {
            const int lm0 = wm * 32 + mf * 16 + gid;
            const int m0 = bm + lm0;
            unsigned long long best0 = 0ull, best1 = 0ull;
#pragma unroll
            for (int nf = 0; nf < 4; ++nf) {
                const int n = bn + wn * 32 + nf * 8 + 2 * tig;
                if (!NG || n < N) {      // N even, n even => pair fully in range
                    float2 bo = *(const float2*)(bout + n);
                    const float* g0 = gumbel + ((size_t)step * NB + m0) * (size_t)NV + n;
                    float2 ga = *(const float2*)g0;
                    float2 gb = *(const float2*)(g0 + (size_t)8 * NV);
                    float4 v = acc[mf][nf];
                    unsigned long long p;
                    p = packmax(v.x + bo.x + ga.x, n);     if (p > best0) best0 = p;
                    p = packmax(v.y + bo.y + ga.y, n + 1); if (p > best0) best0 = p;
                    p = packmax(v.z + bo.x + gb.x, n);     if (p > best1) best1 = p;
                    p = packmax(v.w + bo.y + gb.y, n + 1); if (p > best1) best1 = p;
                }
            }
            if (best0) atomicMax(&rowmax[lm0], best0);
            if (best1) atomicMax(&rowmax[lm0 + 8], best1);
        }
        __syncthreads();
        if (tid < 64 && rowmax[tid])
            atomicMax(&g_amax[bm + tid], rowmax[tid]);
    }
}

// ---------------- GRU elementwise (float4): h_new from G1, G2, biases, h_old ----------------
__global__ void gru_elem(const float* __restrict__ b_ih, const float* __restrict__ b_hh,
                         const float* __restrict__ hOld, float* __restrict__ hNew)
{
    int idx = blockIdx.x * blockDim.x + threadIdx.x;   // NB*DHID/4
    int m = idx >> 8;                 // DHID/4 = 256 float4 per row
    int j = (idx & 255) * 4;
    const float* G1 = g_G1 + (size_t)m * (3 * DHID);
    const float* G2 = g_G2 + (size_t)m * (3 * DHID);

    float4 ir = *(const float4*)(G1 + j);
    float4 iz = *(const float4*)(G1 + DHID + j);
    float4 in_ = *(const float4*)(G1 + 2 * DHID + j);
    float4 hr = *(const float4*)(G2 + j);
    float4 hz = *(const float4*)(G2 + DHID + j);
    float4 hn = *(const float4*)(G2 + 2 * DHID + j);
    float4 bir = *(const float4*)(b_ih + j);
    float4 biz = *(const float4*)(b_ih + DHID + j);
    float4 bin = *(const float4*)(b_ih + 2 * DHID + j);
    float4 bhr = *(const float4*)(b_hh + j);
    float4 bhz = *(const float4*)(b_hh + DHID + j);
    float4 bhn = *(const float4*)(b_hh + 2 * DHID + j);
    float4 ho = *(const float4*)(hOld + (size_t)m * DHID + j);

    float4 res;
#define GRU1(c) { \
        float r = 1.f / (1.f + expf(-((ir.c + bir.c) + (hr.c + bhr.c)))); \
        float z = 1.f / (1.f + expf(-((iz.c + biz.c) + (hz.c + bhz.c)))); \
        float n = tanhf((in_.c + bin.c) + r * (hn.c + bhn.c)); \
        res.c = (1.f - z) * n + z * ho.c; }
    GRU1(x) GRU1(y) GRU1(z) GRU1(w)
#undef GRU1
    *(float4*)(hNew + (size_t)m * DHID + j) = res;
}

// ---------------- finalize step: decode argmax, write one-hot, gather next x ----------------
__global__ void finalize_kernel(const float* __restrict__ emb, float* __restrict__ out, int s) {
    int b = blockIdx.x;
    __shared__ int stok;
    if (threadIdx.x == 0) {
        unsigned long long p = g_amax[b];
        int t = (int)(0xFFFFFFFFu - (unsigned)(p & 0xFFFFFFFFull));
        stok = t;
        g_tok[s * NB + b] = t;
        g_amax[b] = 0ull;
        out[((size_t)b * NS + s) * NV + t] = 1.0f;
    }
    __syncthreads();
    int t = stok;
    for (int k = threadIdx.x; k < DEMB; k += 128)
        g_x[b * DEMB + k] = fmaxf(emb[(size_t)t * DEMB + k], 0.f);
}

// ---------------- msg_lens: last EOS index + 1, else S ----------------
__global__ void lens_kernel(float* __restrict__ out, int out_size) {
    int b = threadIdx.x;
    int len = NS;
    for (int s = NS - 1; s >= 0; --s) {
        if (g_tok[s * NB + b] == EOS_TOK) { len = s + 1; break; }
    }
    if (out_size >= NB * NS * NV + NB)
        out[(size_t)NB * NS * NV + b] = (float)len;
}

// ---------------- launch ----------------
extern "C" void kernel_launch(void* const* d_in, const int* in_sizes, int n_in,
                              void* d_out, int out_size)
{
    const float* image = (const float*)d_in[0];
    const float* W_b   = (const float*)d_in[1];
    const float* emb   = (const float*)d_in[2];
    const float* w_ih  = (const float*)d_in[3];
    const float* w_hh  = (const float*)d_in[4];
    const float* b_ih  = (const float*)d_in[5];
    const float* b_hh  = (const float*)d_in[6];
    const float* W_out = (const float*)d_in[7];
    const float* b_out = (const float*)d_in[8];
    const float* gum   = (const float*)d_in[9];
    float* out = (float*)d_out;

    float *p_h0, *p_h1, *p_x, *p_G1, *p_G2, *p_WbT;
    cudaGetSymbolAddress((void**)&p_h0,  g_h0);
    cudaGetSymbolAddress((void**)&p_h1,  g_h1);
    cudaGetSymbolAddress((void**)&p_x,   g_x);
    cudaGetSymbolAddress((void**)&p_G1,  g_G1);
    cudaGetSymbolAddress((void**)&p_G2,  g_G2);
    cudaGetSymbolAddress((void**)&p_WbT, g_WbT);

    // zero the one-hot region
    long long n4 = (long long)NB * NS * NV / 4;
    zero_out<<<(unsigned)((n4 + 255) / 256), 256>>>((float4*)out, n4);

    // one-time prep
    transpose_wb<<<dim3(DIMG / 32, DHID / 32), dim3(32, 8)>>>(W_b);
    init_kernel<<<NB, 128>>>(emb);

    // h0 = image @ W_b
    mma_gemm<0, false><<<dim3(DHID / 128, NB / 64, 1), 256>>>(
        image, p_WbT, p_h0, DIMG,
        image, p_WbT, p_h0, DIMG,
        DHID, nullptr, nullptr, 0);

    for (int s = 0; s < NS; ++s) {
        const float* hc = (s & 1) ? p_h1 : p_h0;
        float*       hn = (s & 1) ? p_h0 : p_h1;
        // fused gate GEMMs: z=0 -> G1 = x @ w_ih^T (K=512); z=1 -> G2 = h @ w_hh^T (K=1024)
        mma_gemm<0, false><<<dim3(3 * DHID / 128, NB / 64, 2), 256>>>(
            p_x, w_ih, p_G1, DEMB,
            hc,  w_hh, p_G2, DHID,
            3 * DHID, nullptr, nullptr, 0);
        gru_elem<<<(NB * DHID / 4) / 256, 256>>>(b_ih, b_hh, hc, hn);
        // logits + bias + gumbel + argmax
        mma_gemm<1, true><<<dim3((NV + 127) / 128, NB / 64, 1), 256>>>(
            hn, W_out, nullptr, DHID,
            hn, W_out, nullptr, DHID,
            NV, b_out, gum, s);
        finalize_kernel<<<NB, 128>>>(emb, out, s);
    }

    lens_kernel<<<1, 256>>>(out, out_size);
}

// round 9
// speedup vs baseline: 2.8149x; 1.2407x over previous
#include <cuda_runtime.h>
#include <cuda_bf16.h>
#include <cstdint>

#define NB 256
#define NS 32
#define NV 10000
#define DEMB 512
#define DHID 1024
#define DIMG 2048
#define BOS_TOK 1
#define EOS_TOK 2

// ---------------- device scratch (static, no allocations) ----------------
__device__ float g_h0[NB * DHID];
__device__ float g_h1[NB * DHID];
__device__ float g_G1[NB * 3 * DHID];
__device__ float g_G2[NB * 3 * DHID];
__device__ unsigned long long g_amax[NB];
__device__ int g_tok[NS * NB];

// bf16 3-split planes (plane p at offset p*planeElems)
__device__ uint16_t g_pImg [3u * NB * DIMG];
__device__ uint16_t g_pWbT [3u * DHID * DIMG];
__device__ uint16_t g_pWih [3u * 3 * DHID * DEMB];
__device__ uint16_t g_pWhh [3u * 3 * DHID * DHID];
__device__ uint16_t g_pWout[3u * NV * DHID];
__device__ uint16_t g_pX   [3u * NB * DEMB];
__device__ uint16_t g_pHA  [3u * NB * DHID];
__device__ uint16_t g_pHB  [3u * NB * DHID];

// order-preserving (float,index) pack; max => max value, ties => smallest index
__device__ __forceinline__ unsigned long long packmax(float v, int idx) {
    unsigned int b = __float_as_uint(v);
    b = (b & 0x80000000u) ? ~b : (b | 0x80000000u);
    return ((unsigned long long)b << 32) | (unsigned long long)(0xFFFFFFFFu - (unsigned)idx);
}

// ---------------- bf16 3-way split helpers ----------------
__device__ __forceinline__ uint32_t packbf(float hi, float lo) {
    uint32_t r;
    asm("cvt.rn.bf16x2.f32 %0, %1, %2;" : "=r"(r) : "f"(hi), "f"(lo));
    return r;
}
__device__ __forceinline__ float lo16f(uint32_t w) { return __uint_as_float(w << 16); }
__device__ __forceinline__ float hi16f(uint32_t w) { return __uint_as_float(w & 0xFFFF0000u); }

// split pair (x0,x1) -> 3 bf16x2 words (lo half = x0 split, hi half = x1 split)
__device__ __forceinline__ void split3(float x0, float x1, uint32_t& w0, uint32_t& w1, uint32_t& w2) {
    w0 = packbf(x1, x0);
    float r0 = x0 - lo16f(w0), r1 = x1 - hi16f(w0);
    w1 = packbf(r1, r0);
    float s0 = r0 - lo16f(w1), s1 = r1 - hi16f(w1);
    w2 = packbf(s1, s0);
}

// ---------------- mma / ldmatrix / cp.async ----------------
__device__ __forceinline__ void mma_bf16(float4& d, const uint32_t* a, const uint32_t* b) {
    asm volatile(
        "mma.sync.aligned.m16n8k16.row.col.f32.bf16.bf16.f32 "
        "{%0,%1,%2,%3}, {%4,%5,%6,%7}, {%8,%9}, {%0,%1,%2,%3};"
        : "+f"(d.x), "+f"(d.y), "+f"(d.z), "+f"(d.w)
        : "r"(a[0]), "r"(a[1]), "r"(a[2]), "r"(a[3]), "r"(b[0]), "r"(b[1]));
}
__device__ __forceinline__ void ldsm4(uint32_t& r0, uint32_t& r1, uint32_t& r2, uint32_t& r3,
                                      unsigned addr) {
    asm volatile("ldmatrix.sync.aligned.m8n8.x4.shared.b16 {%0,%1,%2,%3}, [%4];"
                 : "=r"(r0), "=r"(r1), "=r"(r2), "=r"(r3) : "r"(addr));
}
__device__ __forceinline__ void cpa16(unsigned dst, const void* src, unsigned srcsz) {
    asm volatile("cp.async.cg.shared.global [%0], [%1], 16, %2;"
                 :: "r"(dst), "l"(src), "r"(srcsz));
}
__device__ __forceinline__ void cpa_commit() {
    asm volatile("cp.async.commit_group;" ::: "memory");
}
__device__ __forceinline__ void cpa_wait0() {
    asm volatile("cp.async.wait_group 0;" ::: "memory");
}

// ---------------- one-time: split a matrix into 3 bf16 planes ----------------
__global__ void split_mat(const float* __restrict__ src, uint16_t* __restrict__ dst, long n2) {
    long i = (long)blockIdx.x * blockDim.x + threadIdx.x;
    if (i >= n2) return;
    float2 v = ((const float2*)src)[i];
    uint32_t w0, w1, w2;
    split3(v.x, v.y, w0, w1, w2);
    uint32_t* d = (uint32_t*)dst;
    d[i] = w0; d[i + n2] = w1; d[i + 2 * n2] = w2;
}

// ---------------- one-time: W_b transpose + split: [DIMG][DHID] -> planes [DHID][DIMG] ----------------
__global__ void transpose_split_wb(const float* __restrict__ Wb) {
    __shared__ float t[32][33];
    int k0 = blockIdx.x * 32;
    int n0 = blockIdx.y * 32;
    for (int i = threadIdx.y; i < 32; i += 8)
        t[i][threadIdx.x] = Wb[(size_t)(k0 + i) * DHID + n0 + threadIdx.x];
    __syncthreads();
    const size_t PS = (size_t)DHID * DIMG;
    for (int i = threadIdx.y; i < 32; i += 8) {
        float v = t[threadIdx.x][i];
        uint32_t w0, w1, w2;
        split3(v, 0.f, w0, w1, w2);
        size_t o = (size_t)(n0 + i) * DIMG + k0 + threadIdx.x;
        g_pWbT[o]          = (uint16_t)(w0 & 0xFFFF);
        g_pWbT[o + PS]     = (uint16_t)(w1 & 0xFFFF);
        g_pWbT[o + 2 * PS] = (uint16_t)(w2 & 0xFFFF);
    }
}

// ---------------- zero the one-hot output ----------------
__global__ void zero_out(float4* o, long long n4) {
    long long i = (long long)blockIdx.x * blockDim.x + threadIdx.x;
    if (i < n4) o[i] = make_float4(0.f, 0.f, 0.f, 0.f);
}

// ---------------- write relu(emb[token]) into g_pX planes ----------------
__device__ __forceinline__ void write_x_planes(const float* __restrict__ emb, int tok, int b, int tid) {
    const int k = tid * 4;                         // 128 threads x 4 = 512
    float4 e = *(const float4*)(emb + (size_t)tok * DEMB + k);
    e.x = fmaxf(e.x, 0.f); e.y = fmaxf(e.y, 0.f);
    e.z = fmaxf(e.z, 0.f); e.w = fmaxf(e.w, 0.f);
    uint32_t a0, a1, a2, b0, b1, b2;
    split3(e.x, e.y, a0, a1, a2);
    split3(e.z, e.w, b0, b1, b2);
    const long PS = (long)NB * DEMB / 2;
    uint32_t* d = (uint32_t*)g_pX;
    long o = ((long)b * DEMB + k) >> 1;
    d[o] = a0;          d[o + 1] = b0;
    d[o + PS] = a1;     d[o + 1 + PS] = b1;
    d[o + 2 * PS] = a2; d[o + 1 + 2 * PS] = b2;
}

// ---------------- init: x0 planes = relu(emb[BOS]), amax reset ----------------
__global__ void init_kernel(const float* __restrict__ emb) {
    int b = blockIdx.x;
    if (threadIdx.x == 0) g_amax[b] = 0ull;
    write_x_planes(emb, BOS_TOK, b, threadIdx.x);
}

// =====================================================================
// bf16x3 (6-product) tensor-core GEMM:  C[M,N] = A[M,K]*B[N,K]^T  (fp32-faithful)
// A, B given as 3 pre-split bf16 planes. CTA tile 64x128, 8 warps,
// warp tile 32x32. K staged in tiles of 32 via cp.async (double-buffered),
// smem rows of 64B with XOR swizzle; fragments via ldmatrix.x4.
// EPI=0: store fp32 C. EPI=1: +bias+gumbel+argmax. EPI=2: fp32 C + h planes.
// =====================================================================
template<int EPI, bool NG>
__global__ __launch_bounds__(256, 2)
void bgemm(const uint16_t* __restrict__ A0, size_t sA0, const uint16_t* __restrict__ B0, size_t sB0,
           float* C0, int K0,
           const uint16_t* __restrict__ A1, size_t sA1, const uint16_t* __restrict__ B1, size_t sB1,
           float* C1, int K1,
           int Nn, const float* __restrict__ bout, const float* __restrict__ gumbel, int step,
           uint16_t* hpl)
{
    const uint16_t* A; const uint16_t* B; float* C; int K; size_t sA, sB;
    if (blockIdx.z == 0) { A = A0; sA = sA0; B = B0; sB = sB0; C = C0; K = K0; }
    else                 { A = A1; sA = sA1; B = B1; sB = sB1; C = C1; K = K1; }

    extern __shared__ uint8_t dynraw[];
    unsigned dynb = (unsigned)__cvta_generic_to_shared(dynraw);
    dynb = (dynb + 1023u) & ~1023u;
    __shared__ unsigned long long rowmax[64];

    const int tid  = threadIdx.x;
    const int lane = tid & 31;
    const int wid  = tid >> 5;
    const int wm = wid >> 2;          // 0..1
    const int wn = wid & 3;           // 0..3
    const int gid = lane >> 2;        // 0..7
    const int tig = lane & 3;         // 0..3
    const int bm = blockIdx.y * 64;
    const int bn = blockIdx.x * 128;

    // ---- staging ids: A 64 rows x 4 chunks; B 128 rows x 4 chunks (2 tasks) ----
    const int rowA = tid >> 2, chA = tid & 3;
    const int rowB = tid >> 2, chB = tid & 3;            // + task*64 rows
    const unsigned soffA = (unsigned)(rowA * 64 + ((chA ^ ((rowA >> 1) & 3)) << 4));
    const unsigned soffB = (unsigned)(rowB * 64 + ((chB ^ ((rowB >> 1) & 3)) << 4));

    const uint16_t* Agp  = A + (size_t)(bm + rowA) * K + chA * 8;
    const uint16_t* Bgp0 = B + (size_t)(bn + rowB) * K + chB * 8;
    const uint16_t* Bgp1 = Bgp0 + (size_t)64 * K;
    const unsigned n0sz = (!NG || (bn + rowB) < Nn) ? 16u : 0u;
    const unsigned n1sz = (!NG || (bn + rowB + 64) < Nn) ? 16u : 0u;

    // ---- ldmatrix per-lane offsets (kstep 0); XOR 32 selects kstep 1 ----
    unsigned aOff[2], bOff[2];
    {
        const int ra = wm * 32 + (lane & 7) + ((lane >> 3) & 1) * 8;
        const int ca = (lane >> 4) & 1;
#pragma unroll
        for (int mf = 0; mf < 2; ++mf) {
            int r = ra + mf * 16;
            aOff[mf] = (unsigned)(r * 64 + ((ca ^ ((r >> 1) & 3)) << 4));
        }
        const int rb = wn * 32 + ((lane >> 4) & 1) * 8 + (lane & 7);
        const int cb = (lane >> 3) & 1;
#pragma unroll
        for (int nfp = 0; nfp < 2; ++nfp) {
            int r = rb + nfp * 16;
            bOff[nfp] = (unsigned)(r * 64 + ((cb ^ ((r >> 1) & 3)) << 4));
        }
    }

    float4 acc[2][4];
#pragma unroll
    for (int i = 0; i < 2; i++)
#pragma unroll
        for (int j = 0; j < 4; j++) acc[i][j] = make_float4(0.f, 0.f, 0.f, 0.f);

    auto STAGE = [&](int kt, int buf) {
        const unsigned base = dynb + (unsigned)buf * 36864u;
        const uint16_t* ap  = Agp  + kt * 32;
        const uint16_t* bp0 = Bgp0 + kt * 32;
        const uint16_t* bp1 = Bgp1 + kt * 32;
#pragma unroll
        for (int p = 0; p < 3; ++p)
            cpa16(base + (unsigned)p * 4096u + soffA, ap + (size_t)p * sA, 16u);
        const unsigned bb = base + 12288u;
#pragma unroll
        for (int p = 0; p < 3; ++p) {
            cpa16(bb + (unsigned)p * 8192u + soffB,          bp0 + (size_t)p * sB, n0sz);
            cpa16(bb + (unsigned)p * 8192u + 4096u + soffB,  bp1 + (size_t)p * sB, n1sz);
        }
        cpa_commit();
    };

    if (EPI == 1 && tid < 64) rowmax[tid] = 0ull;
    STAGE(0, 0);
    cpa_wait0();
    __syncthreads();

    const int KT = K >> 5;
    for (int kt = 0; kt < KT; ++kt) {
        if (kt + 1 < KT) STAGE(kt + 1, (kt + 1) & 1);

        const unsigned ab = dynb + (unsigned)(kt & 1) * 36864u;
        const unsigned bb = ab + 12288u;
#pragma unroll
        for (int kstep = 0; kstep < 2; ++kstep) {
            const unsigned kx = (unsigned)kstep << 5;
            uint32_t aF[3][2][4];
#pragma unroll
            for (int p = 0; p < 3; ++p)
#pragma unroll
                for (int mf = 0; mf < 2; ++mf)
                    ldsm4(aF[p][mf][0], aF[p][mf][1], aF[p][mf][2], aF[p][mf][3],
                          ab + (unsigned)p * 4096u + (aOff[mf] ^ kx));

            uint32_t bF[4][2];
            auto LDB = [&](int p) {
#pragma unroll
                for (int nfp = 0; nfp < 2; ++nfp) {
                    uint32_t r0, r1, r2, r3;
                    ldsm4(r0, r1, r2, r3, bb + (unsigned)p * 8192u + (bOff[nfp] ^ kx));
                    bF[2 * nfp][0] = r0;     bF[2 * nfp][1] = r1;
                    bF[2 * nfp + 1][0] = r2; bF[2 * nfp + 1][1] = r3;
                }
            };
            auto PROD = [&](int ap) {
#pragma unroll
                for (int mf = 0; mf < 2; ++mf)
#pragma unroll
                    for (int nf = 0; nf < 4; ++nf)
                        mma_bf16(acc[mf][nf], aF[ap][mf], bF[nf]);
            };
            // smallest terms first, a0*b0 last
            LDB(2); PROD(0);            // a0*b2
            LDB(1); PROD(1); PROD(0);   // a1*b1, a0*b1
            LDB(0); PROD(2); PROD(1); PROD(0);  // a2*b0, a1*b0, a0*b0
        }
        cpa_wait0();
        __syncthreads();
    }

    if (EPI == 0 || EPI == 2) {
#pragma unroll
        for (int mf = 0; mf < 2; ++mf) {
            const int row = bm + wm * 32 + mf * 16 + gid;
#pragma unroll
            for (int nf = 0; nf < 4; ++nf) {
                const int col = bn + wn * 32 + nf * 8 + 2 * tig;
                float4 v = acc[mf][nf];
                *(float2*)(C + (size_t)row * Nn + col)       = make_float2(v.x, v.y);
                *(float2*)(C + (size_t)(row + 8) * Nn + col) = make_float2(v.z, v.w);
                if (EPI == 2) {
                    const long PSH = (long)NB * DHID / 2;
                    uint32_t* d = (uint32_t*)hpl;
                    uint32_t w0, w1, w2;
                    split3(v.x, v.y, w0, w1, w2);
                    long o = ((long)row * Nn + col) >> 1;
                    d[o] = w0; d[o + PSH] = w1; d[o + 2 * PSH] = w2;
                    split3(v.z, v.w, w0, w1, w2);
                    o = ((long)(row + 8) * Nn + col) >> 1;
                    d[o] = w0; d[o + PSH] = w1; d[o + 2 * PSH] = w2;
                }
            }
        }
    } else {
        // fused +bias +gumbel + packed argmax
#pragma unroll
        for (int mf = 0; mf < 2; ++mf) {
            const int lm0 = wm * 32 + mf * 16 + gid;
            const int m0 = bm + lm0;
            unsigned long long best0 = 0ull, best1 = 0ull;
#pragma unroll
            for (int nf = 0; nf < 4; ++nf) {
                const int col = bn + wn * 32 + nf * 8 + 2 * tig;
                if (!NG || col < Nn) {      // Nn even, col even => pair fully valid
                    float2 bo = *(const float2*)(bout + col);
                    const float* g0 = gumbel + ((size_t)step * NB + m0) * (size_t)NV + col;
                    float2 ga = *(const float2*)g0;
                    float2 gb = *(const float2*)(g0 + (size_t)8 * NV);
                    float4 v = acc[mf][nf];
                    unsigned long long p;
                    p = packmax(v.x + bo.x + ga.x, col);     if (p > best0) best0 = p;
                    p = packmax(v.y + bo.y + ga.y, col + 1); if (p > best0) best0 = p;
                    p = packmax(v.z + bo.x + gb.x, col);     if (p > best1) best1 = p;
                    p = packmax(v.w + bo.y + gb.y, col + 1); if (p > best1) best1 = p;
                }
            }
            if (best0) atomicMax(&rowmax[lm0], best0);
            if (best1) atomicMax(&rowmax[lm0 + 8], best1);
        }
        __syncthreads();
        if (tid < 64 && rowmax[tid])
            atomicMax(&g_amax[bm + tid], rowmax[tid]);
    }
}

// ---------------- GRU elementwise: h_new (fp32 + bf16 planes) ----------------
__global__ void gru_elem(const float* __restrict__ b_ih, const float* __restrict__ b_hh,
                         const float* __restrict__ hOld, float* __restrict__ hNew,
                         uint16_t* __restrict__ hpl)
{
    int idx = blockIdx.x * blockDim.x + threadIdx.x;   // NB*DHID/4
    int m = idx >> 8;
    int j = (idx & 255) * 4;
    const float* G1 = g_G1 + (size_t)m * (3 * DHID);
    const float* G2 = g_G2 + (size_t)m * (3 * DHID);

    float4 ir = *(const float4*)(G1 + j);
    float4 iz = *(const float4*)(G1 + DHID + j);
    float4 in_ = *(const float4*)(G1 + 2 * DHID + j);
    float4 hr = *(const float4*)(G2 + j);
    float4 hz = *(const float4*)(G2 + DHID + j);
    float4 hn = *(const float4*)(G2 + 2 * DHID + j);
    float4 bir = *(const float4*)(b_ih + j);
    float4 biz = *(const float4*)(b_ih + DHID + j);
    float4 bin = *(const float4*)(b_ih + 2 * DHID + j);
    float4 bhr = *(const float4*)(b_hh + j);
    float4 bhz = *(const float4*)(b_hh + DHID + j);
    float4 bhn = *(const float4*)(b_hh + 2 * DHID + j);
    float4 ho = *(const float4*)(hOld + (size_t)m * DHID + j);

    float4 res;
#define GRU1(c) { \
        float r = 1.f / (1.f + expf(-((ir.c + bir.c) + (hr.c + bhr.c)))); \
        float z = 1.f / (1.f + expf(-((iz.c + biz.c) + (hz.c + bhz.c)))); \
        float n = tanhf((in_.c + bin.c) + r * (hn.c + bhn.c)); \
        res.c = (1.f - z) * n + z * ho.c; }
    GRU1(x) GRU1(y) GRU1(z) GRU1(w)
#undef GRU1
    *(float4*)(hNew + (size_t)m * DHID + j) = res;

    const long PSH = (long)NB * DHID / 2;
    uint32_t a0, a1, a2, b0, b1, b2;
    split3(res.x, res.y, a0, a1, a2);
    split3(res.z, res.w, b0, b1, b2);
    uint32_t* d = (uint32_t*)hpl;
    long o = ((long)m * DHID + j) >> 1;
    d[o] = a0;           d[o + 1] = b0;
    d[o + PSH] = a1;     d[o + 1 + PSH] = b1;
    d[o + 2 * PSH] = a2; d[o + 1 + 2 * PSH] = b2;
}

// ---------------- finalize step: decode argmax, one-hot, next-x planes ----------------
__global__ void finalize_kernel(const float* __restrict__ emb, float* __restrict__ out, int s) {
    int b = blockIdx.x;
    __shared__ int stok;
    if (threadIdx.x == 0) {
        unsigned long long p = g_amax[b];
        int t = (int)(0xFFFFFFFFu - (unsigned)(p & 0xFFFFFFFFull));
        stok = t;
        g_tok[s * NB + b] = t;
        g_amax[b] = 0ull;
        out[((size_t)b * NS + s) * NV + t] = 1.0f;
    }
    __syncthreads();
    write_x_planes(emb, stok, b, threadIdx.x);
}

// ---------------- msg_lens: last EOS index + 1, else S ----------------
__global__ void lens_kernel(float* __restrict__ out, int out_size) {
    int b = threadIdx.x;
    int len = NS;
    for (int s = NS - 1; s >= 0; --s) {
        if (g_tok[s * NB + b] == EOS_TOK) { len = s + 1; break; }
    }
    if (out_size >= NB * NS * NV + NB)
        out[(size_t)NB * NS * NV + b] = (float)len;
}

// ---------------- launch ----------------
extern "C" void kernel_launch(void* const* d_in, const int* in_sizes, int n_in,
                              void* d_out, int out_size)
{
    const float* image = (const float*)d_in[0];
    const float* W_b   = (const float*)d_in[1];
    const float* emb   = (const float*)d_in[2];
    const float* w_ih  = (const float*)d_in[3];
    const float* w_hh  = (const float*)d_in[4];
    const float* b_ih  = (const float*)d_in[5];
    const float* b_hh  = (const float*)d_in[6];
    const float* W_out = (const float*)d_in[7];
    const float* b_out = (const float*)d_in[8];
    const float* gum   = (const float*)d_in[9];
    float* out = (float*)d_out;

    float *p_h0, *p_h1, *p_G1, *p_G2;
    uint16_t *pImg, *pWbT, *pWih, *pWhh, *pWout, *pX, *pHA, *pHB;
    cudaGetSymbolAddress((void**)&p_h0,  g_h0);
    cudaGetSymbolAddress((void**)&p_h1,  g_h1);
    cudaGetSymbolAddress((void**)&p_G1,  g_G1);
    cudaGetSymbolAddress((void**)&p_G2,  g_G2);
    cudaGetSymbolAddress((void**)&pImg,  g_pImg);
    cudaGetSymbolAddress((void**)&pWbT,  g_pWbT);
    cudaGetSymbolAddress((void**)&pWih,  g_pWih);
    cudaGetSymbolAddress((void**)&pWhh,  g_pWhh);
    cudaGetSymbolAddress((void**)&pWout, g_pWout);
    cudaGetSymbolAddress((void**)&pX,    g_pX);
    cudaGetSymbolAddress((void**)&pHA,   g_pHA);
    cudaGetSymbolAddress((void**)&pHB,   g_pHB);

    const int SHB = 73728 + 1024;   // 2 x 36 KB stages + alignment pad
    cudaFuncSetAttribute(bgemm<0, false>, cudaFuncAttributeMaxDynamicSharedMemorySize, SHB);
    cudaFuncSetAttribute(bgemm<1, true>,  cudaFuncAttributeMaxDynamicSharedMemorySize, SHB);
    cudaFuncSetAttribute(bgemm<2, false>, cudaFuncAttributeMaxDynamicSharedMemorySize, SHB);

    // zero the one-hot region
    long long n4 = (long long)NB * NS * NV / 4;
    zero_out<<<(unsigned)((n4 + 255) / 256), 256>>>((float4*)out, n4);

    // one-time: weight/activation pre-splits
    transpose_split_wb<<<dim3(DIMG / 32, DHID / 32), dim3(32, 8)>>>(W_b);
    {
        long n2;
        n2 = (long)3 * DHID * DEMB / 2;
        split_mat<<<(unsigned)((n2 + 255) / 256), 256>>>(w_ih, pWih, n2);
        n2 = (long)3 * DHID * DHID / 2;
        split_mat<<<(unsigned)((n2 + 255) / 256), 256>>>(w_hh, pWhh, n2);
        n2 = (long)NV * DHID / 2;
        split_mat<<<(unsigned)((n2 + 255) / 256), 256>>>(W_out, pWout, n2);
        n2 = (long)NB * DIMG / 2;
        split_mat<<<(unsigned)((n2 + 255) / 256), 256>>>(image, pImg, n2);
    }
    init_kernel<<<NB, 128>>>(emb);

    const size_t sImg  = (size_t)NB * DIMG;
    const size_t sWbT  = (size_t)DHID * DIMG;
    const size_t sWih  = (size_t)3 * DHID * DEMB;
    const size_t sWhh  = (size_t)3 * DHID * DHID;
    const size_t sWout = (size_t)NV * DHID;
    const size_t sX    = (size_t)NB * DEMB;
    const size_t sH    = (size_t)NB * DHID;

    // h0 = image @ W_b -> g_h0 fp32 + pHA planes
    bgemm<2, false><<<dim3(DHID / 128, NB / 64, 1), 256, SHB>>>(
        pImg, sImg, pWbT, sWbT, p_h0, DIMG,
        pImg, sImg, pWbT, sWbT, p_h0, DIMG,
        DHID, nullptr, nullptr, 0, pHA);

    for (int s = 0; s < NS; ++s) {
        const float* hc = (s & 1) ? p_h1 : p_h0;
        float*       hn = (s & 1) ? p_h0 : p_h1;
        uint16_t* pHc = (s & 1) ? pHB : pHA;
        uint16_t* pHn = (s & 1) ? pHA : pHB;

        // gates: z=0 -> G1 = x @ w_ih^T (K=512); z=1 -> G2 = h @ w_hh^T (K=1024)
        bgemm<0, false><<<dim3(3 * DHID / 128, NB / 64, 2), 256, SHB>>>(
            pX,  sX, pWih, sWih, p_G1, DEMB,
            pHc, sH, pWhh, sWhh, p_G2, DHID,
            3 * DHID, nullptr, nullptr, 0, nullptr);
        gru_elem<<<(NB * DHID / 4) / 256, 256>>>(b_ih, b_hh, hc, hn, pHn);
        // logits + bias + gumbel + argmax
        bgemm<1, true><<<dim3((NV + 127) / 128, NB / 64, 1), 256, SHB>>>(
            pHn, sH, pWout, sWout, nullptr, DHID,
            pHn, sH, pWout, sWout, nullptr, DHID,
            NV, b_out, gum, s, nullptr);
        finalize_kernel<<<NB, 128>>>(emb, out, s);
    }

    lens_kernel<<<1, 256>>>(out, out_size);
}